// round 1
// baseline (speedup 1.0000x reference)
#include <cuda_runtime.h>
#include <math.h>

#define N0v 20000
#define N1v 20000
#define NNODE 40000
#define F0v 512
#define HIDv 64
#define EPM 200000
#define BTv 8192
#define NPv 4

// ---------------- scratch (static device globals; no allocation) -------------
__device__ float g_feat[NNODE * HIDv];            // 10.24 MB
__device__ float g_eft[NPv * EPM * HIDv];         // 204.8 MB
__device__ float g_e[NPv * EPM * 8];              // 25.6 MB (e, then a in-place)
__device__ float g_m[NPv * BTv * 8];              // segment max
__device__ float g_s[NPv * BTv * 8];              // segment sum of a
__device__ float g_ret[NPv * BTv * HIDv];         // segment sum of w*eft -> elu'd outs
__device__ float g_fr[2 * 3 * 32 * 2];            // [side][l][k][re,im]
__device__ float g_score[4];

__device__ __forceinline__ void atomicMaxF(float* addr, float v) {
    if (v >= 0.f) atomicMax((int*)addr, __float_as_int(v));
    else          atomicMin((unsigned int*)addr, __float_as_uint(v));
}

// ---------------- init: zero accumulators, compute rotation chain ------------
__global__ void k_init(const float* __restrict__ r_vec) {
    int idx = blockIdx.x * blockDim.x + threadIdx.x;
    if (idx < NPv * BTv * 8) {
        g_s[idx] = 0.f;
        g_m[idx] = __int_as_float(0xFF800000);   // -inf
    }
    if (idx < NPv * BTv * HIDv) g_ret[idx] = 0.f;
    if (idx < 4) g_score[idx] = 0.f;
    if (idx < 32) {
        int k = idx;
        float rr = r_vec[k * 2 + 0], ri = r_vec[k * 2 + 1];
        float nm = sqrtf(rr * rr + ri * ri);
        float cr = rr / nm, ci = ri / nm;            // rfull[0] = (cr,ci), rfull[1] = (cr,-ci)
        // user etypes {0,1}: fr[2]=(1,0); fr[1]=fr[2]*rfull[1]; fr[0]=fr[1]*rfull[0]
        float u1r = cr,  u1i = -ci;
        float u0r = u1r * cr - u1i * ci;
        float u0i = u1r * ci + u1i * cr;
        g_fr[(0 * 3 + 0) * 64 + 2 * k] = u0r; g_fr[(0 * 3 + 0) * 64 + 2 * k + 1] = u0i;
        g_fr[(0 * 3 + 1) * 64 + 2 * k] = u1r; g_fr[(0 * 3 + 1) * 64 + 2 * k + 1] = u1i;
        g_fr[(0 * 3 + 2) * 64 + 2 * k] = 1.f; g_fr[(0 * 3 + 2) * 64 + 2 * k + 1] = 0.f;
        // item etypes {1,0}: fr[1]=rfull[0]; fr[0]=fr[1]*rfull[1]
        float i1r = cr,  i1i = ci;
        float i0r = i1r * cr - i1i * (-ci);
        float i0i = i1r * (-ci) + i1i * cr;
        g_fr[(1 * 3 + 0) * 64 + 2 * k] = i0r; g_fr[(1 * 3 + 0) * 64 + 2 * k + 1] = i0i;
        g_fr[(1 * 3 + 1) * 64 + 2 * k] = i1r; g_fr[(1 * 3 + 1) * 64 + 2 * k + 1] = i1i;
        g_fr[(1 * 3 + 2) * 64 + 2 * k] = 1.f; g_fr[(1 * 3 + 2) * 64 + 2 * k + 1] = 0.f;
    }
}

// ---------------- towers: Linear(512->64)+GELU+Linear(64->64)+res+LN ---------
__global__ __launch_bounds__(256) void k_tower(
    const float* __restrict__ feats0, const float* __restrict__ feats1,
    const float* __restrict__ pw0, const float* __restrict__ pb0,
    const float* __restrict__ w20, const float* __restrict__ b20,
    const float* __restrict__ gg0, const float* __restrict__ be0,
    const float* __restrict__ pw1, const float* __restrict__ pb1,
    const float* __restrict__ w21, const float* __restrict__ b21,
    const float* __restrict__ gg1, const float* __restrict__ be1,
    const int* __restrict__ idx0, const int* __restrict__ idx1)
{
    __shared__ float xs[64][34];   // transposed x chunk [k][node]
    __shared__ float ws[64][64];   // weight chunk [k][col]
    __shared__ float hs[64][34];   // transposed gelu(z) [k][node]

    const int NB0 = N0v / 32;
    int bt = blockIdx.x;
    int tower = (bt >= NB0) ? 1 : 0;
    int nbase = (tower ? bt - NB0 : bt) * 32;
    const float* X  = tower ? feats1 : feats0;
    const float* PW = tower ? pw1 : pw0;
    const float* PB = tower ? pb1 : pb0;
    const float* W2 = tower ? w21 : w20;
    const float* B2 = tower ? b21 : b20;
    const float* GG = tower ? gg1 : gg0;
    const float* BE = tower ? be1 : be0;
    const int*  IDX = tower ? idx1 : idx0;

    int tid  = threadIdx.x;
    int col  = (tid & 15) * 4;     // 4 output cols
    int nloc = (tid >> 4) * 2;     // 2 nodes
    int ldn  = tid >> 3;           // loader: node 0..31
    int ldk  = (tid & 7) * 8;      // loader: k offset
    int wr   = tid >> 2;           // weight loader: row 0..63
    int wc   = (tid & 3) * 16;

    float acc0[4] = {0.f,0.f,0.f,0.f}, acc1[4] = {0.f,0.f,0.f,0.f};

    for (int kc = 0; kc < F0v; kc += 64) {
        const float* xrow = X + (size_t)(nbase + ldn) * F0v + kc + ldk;
        float4 a4 = *(const float4*)(xrow);
        float4 b4 = *(const float4*)(xrow + 4);
        xs[ldk + 0][ldn] = a4.x; xs[ldk + 1][ldn] = a4.y;
        xs[ldk + 2][ldn] = a4.z; xs[ldk + 3][ldn] = a4.w;
        xs[ldk + 4][ldn] = b4.x; xs[ldk + 5][ldn] = b4.y;
        xs[ldk + 6][ldn] = b4.z; xs[ldk + 7][ldn] = b4.w;
        const float4* wsrc = (const float4*)(PW + (size_t)(kc + wr) * HIDv + wc);
        float4* wdst = (float4*)&ws[wr][wc];
        wdst[0] = wsrc[0]; wdst[1] = wsrc[1]; wdst[2] = wsrc[2]; wdst[3] = wsrc[3];
        __syncthreads();
        #pragma unroll
        for (int kk = 0; kk < 64; kk++) {
            float2 xv = *(float2*)&xs[kk][nloc];
            float4 wv = *(float4*)&ws[kk][col];
            acc0[0] += xv.x * wv.x; acc0[1] += xv.x * wv.y;
            acc0[2] += xv.x * wv.z; acc0[3] += xv.x * wv.w;
            acc1[0] += xv.y * wv.x; acc1[1] += xv.y * wv.y;
            acc1[2] += xv.y * wv.z; acc1[3] += xv.y * wv.w;
        }
        __syncthreads();
    }

    float z0[4], z1[4];
    #pragma unroll
    for (int j = 0; j < 4; j++) {
        z0[j] = acc0[j] + PB[col + j];
        z1[j] = acc1[j] + PB[col + j];
    }
    // exact GELU -> hs (transposed); load w2 into ws
    #pragma unroll
    for (int j = 0; j < 4; j++) {
        float h0 = 0.5f * z0[j] * (1.f + erff(z0[j] * 0.70710678118654752f));
        float h1 = 0.5f * z1[j] * (1.f + erff(z1[j] * 0.70710678118654752f));
        hs[col + j][nloc]     = h0;
        hs[col + j][nloc + 1] = h1;
    }
    {
        const float4* wsrc = (const float4*)(W2 + (size_t)wr * HIDv + wc);
        float4* wdst = (float4*)&ws[wr][wc];
        wdst[0] = wsrc[0]; wdst[1] = wsrc[1]; wdst[2] = wsrc[2]; wdst[3] = wsrc[3];
    }
    __syncthreads();

    float y0[4] = {0.f,0.f,0.f,0.f}, y1[4] = {0.f,0.f,0.f,0.f};
    #pragma unroll
    for (int kk = 0; kk < 64; kk++) {
        float2 xv = *(float2*)&hs[kk][nloc];
        float4 wv = *(float4*)&ws[kk][col];
        y0[0] += xv.x * wv.x; y0[1] += xv.x * wv.y;
        y0[2] += xv.x * wv.z; y0[3] += xv.x * wv.w;
        y1[0] += xv.y * wv.x; y1[1] += xv.y * wv.y;
        y1[2] += xv.y * wv.z; y1[3] += xv.y * wv.w;
    }
    #pragma unroll
    for (int j = 0; j < 4; j++) {
        y0[j] += B2[col + j] + z0[j];   // residual uses pre-GELU z
        y1[j] += B2[col + j] + z1[j];
    }
    // LayerNorm over 64 cols: reduce across the 16 threads owning this node pair
    float s10 = y0[0] + y0[1] + y0[2] + y0[3];
    float s20 = y0[0]*y0[0] + y0[1]*y0[1] + y0[2]*y0[2] + y0[3]*y0[3];
    float s11 = y1[0] + y1[1] + y1[2] + y1[3];
    float s21 = y1[0]*y1[0] + y1[1]*y1[1] + y1[2]*y1[2] + y1[3]*y1[3];
    #pragma unroll
    for (int m = 1; m < 16; m <<= 1) {
        s10 += __shfl_xor_sync(0xffffffffu, s10, m);
        s20 += __shfl_xor_sync(0xffffffffu, s20, m);
        s11 += __shfl_xor_sync(0xffffffffu, s11, m);
        s21 += __shfl_xor_sync(0xffffffffu, s21, m);
    }
    float mu0 = s10 * (1.f / 64.f), mu1 = s11 * (1.f / 64.f);
    float rs0 = 1.f / sqrtf(s20 * (1.f / 64.f) - mu0 * mu0 + 1e-5f);
    float rs1 = 1.f / sqrtf(s21 * (1.f / 64.f) - mu1 * mu1 + 1e-5f);
    int gn0 = IDX[nbase + nloc];
    int gn1 = IDX[nbase + nloc + 1];
    float4 o0, o1;
    o0.x = (y0[0]-mu0)*rs0*GG[col+0] + BE[col+0];
    o0.y = (y0[1]-mu0)*rs0*GG[col+1] + BE[col+1];
    o0.z = (y0[2]-mu0)*rs0*GG[col+2] + BE[col+2];
    o0.w = (y0[3]-mu0)*rs0*GG[col+3] + BE[col+3];
    o1.x = (y1[0]-mu1)*rs1*GG[col+0] + BE[col+0];
    o1.y = (y1[1]-mu1)*rs1*GG[col+1] + BE[col+1];
    o1.z = (y1[2]-mu1)*rs1*GG[col+2] + BE[col+2];
    o1.w = (y1[3]-mu1)*rs1*GG[col+3] + BE[col+3];
    *(float4*)&g_feat[(size_t)gn0 * HIDv + col] = o0;
    *(float4*)&g_feat[(size_t)gn1 * HIDv + col] = o1;
}

// ---------------- metapath pass 1: gather, rotate, mean, attn logits, segmax -
__global__ __launch_bounds__(256) void k_mp1(
    const int* __restrict__ emi_u, const int* __restrict__ tgt_u,
    const int* __restrict__ emi_i, const int* __restrict__ tgt_i,
    const float* __restrict__ attn_u, const float* __restrict__ attn_i)
{
    int gw = blockIdx.x * (blockDim.x >> 5) + (threadIdx.x >> 5);
    int lane = threadIdx.x & 31;
    if (gw >= NPv * EPM) return;
    int p = gw / EPM;
    int i = gw - p * EPM;
    int side = p >> 1;
    int pl = p & 1;
    const int*  emi  = side ? emi_i  : emi_u;
    const int*  tgt  = side ? tgt_i  : tgt_u;
    const float* attn = side ? attn_i : attn_u;

    int n = (lane < 3) ? emi[((size_t)pl * EPM + i) * 3 + lane] : 0;
    float re = 0.f, im = 0.f;
    #pragma unroll
    for (int l = 0; l < 3; l++) {
        int nl = __shfl_sync(0xffffffffu, n, l);
        float2 v  = *(const float2*)&g_feat[(size_t)nl * HIDv + lane * 2];
        float2 fr = *(const float2*)&g_fr[((side * 3 + l) * 32 + lane) * 2];
        re += v.x * fr.x - v.y * fr.y;
        im += v.x * fr.y + v.y * fr.x;
    }
    re *= (1.f / 3.f);
    im *= (1.f / 3.f);
    *(float2*)&g_eft[(size_t)gw * HIDv + lane * 2] = make_float2(re, im);

    int h  = lane >> 2;
    int d0 = (lane & 3) * 2;
    float2 av = *(const float2*)&attn[(pl * 8 + h) * 8 + d0];
    float ep = re * av.x + im * av.y;
    ep += __shfl_xor_sync(0xffffffffu, ep, 1);
    ep += __shfl_xor_sync(0xffffffffu, ep, 2);
    if ((lane & 3) == 0) {
        float ev = ep > 0.f ? ep : 0.01f * ep;        // leaky_relu
        g_e[(size_t)gw * 8 + h] = ev;
        int t = tgt[(size_t)pl * EPM + i];
        atomicMaxF(&g_m[((size_t)p * BTv + t) * 8 + h], ev);
    }
}

// ---------------- metapath pass 2: a = exp(e - m); segsum(a) -----------------
__global__ __launch_bounds__(256) void k_mp2(
    const int* __restrict__ tgt_u, const int* __restrict__ tgt_i)
{
    int idx = blockIdx.x * blockDim.x + threadIdx.x;
    if (idx >= NPv * EPM * 8) return;
    int h = idx & 7;
    int r = idx >> 3;
    int p = r / EPM;
    int i = r - p * EPM;
    int t = (p < 2) ? tgt_u[(size_t)p * EPM + i] : tgt_i[(size_t)(p - 2) * EPM + i];
    float mv = g_m[((size_t)p * BTv + t) * 8 + h];
    if (!isfinite(mv)) mv = 0.f;
    float a = expf(g_e[idx] - mv);
    g_e[idx] = a;
    atomicAdd(&g_s[((size_t)p * BTv + t) * 8 + h], a);
}

// ---------------- metapath pass 3: ret[tgt] += (a/s) * eft -------------------
__global__ __launch_bounds__(256) void k_mp3(
    const int* __restrict__ tgt_u, const int* __restrict__ tgt_i)
{
    int idx = blockIdx.x * blockDim.x + threadIdx.x;
    if (idx >= NPv * EPM * 16) return;
    int q = idx & 15;                 // float4 slot
    int r = idx >> 4;                 // global instance index
    int p = r / EPM;
    int i = r - p * EPM;
    int h = q >> 1;
    int t = (p < 2) ? tgt_u[(size_t)p * EPM + i] : tgt_i[(size_t)(p - 2) * EPM + i];
    float a  = g_e[(size_t)r * 8 + h];
    float sd = g_s[((size_t)p * BTv + t) * 8 + h];
    float w  = a / (sd + 1e-9f);
    float4 v = *(const float4*)&g_eft[(size_t)r * HIDv + q * 4];
    float4 wv = make_float4(w * v.x, w * v.y, w * v.z, w * v.w);
    atomicAdd((float4*)&g_ret[((size_t)p * BTv + t) * HIDv + q * 4], wv);
}

// ---------------- elu + semantic attention scores ----------------------------
__global__ __launch_bounds__(128) void k_sem(
    const float* __restrict__ su_w1, const float* __restrict__ su_b1, const float* __restrict__ su_w2,
    const float* __restrict__ si_w1, const float* __restrict__ si_b1, const float* __restrict__ si_w2)
{
    __shared__ float w1s[64 * 128];
    __shared__ float v[64];
    __shared__ float red[4];
    int p = blockIdx.y;
    const float* w1 = (p < 2) ? su_w1 : si_w1;
    const float* b1 = (p < 2) ? su_b1 : si_b1;
    const float* w2 = (p < 2) ? su_w2 : si_w2;
    int tid = threadIdx.x;
    for (int k = tid; k < 2048; k += 128)
        ((float4*)w1s)[k] = ((const float4*)w1)[k];
    float rb1 = b1[tid], rw2 = w2[tid];
    float lsum = 0.f;
    __syncthreads();
    for (int bb = 0; bb < 32; bb++) {
        int b = blockIdx.x * 32 + bb;
        if (tid < 64) {
            size_t off = ((size_t)p * BTv + b) * HIDv + tid;
            float x = g_ret[off];
            float el = x > 0.f ? x : expf(x) - 1.f;   // elu
            g_ret[off] = el;                          // persist for final stage
            v[tid] = el;
        }
        __syncthreads();
        float acc = rb1;
        #pragma unroll
        for (int k = 0; k < 64; k++) acc += v[k] * w1s[k * 128 + tid];
        lsum += tanhf(acc) * rw2;
        __syncthreads();
    }
    #pragma unroll
    for (int m = 16; m; m >>= 1) lsum += __shfl_xor_sync(0xffffffffu, lsum, m);
    int w = tid >> 5, ln = tid & 31;
    if (ln == 0) red[w] = lsum;
    __syncthreads();
    if (tid == 0) atomicAdd(&g_score[p], red[0] + red[1] + red[2] + red[3]);
}

// ---------------- beta softmax, fuse sides, ProductMLP, softmax --------------
__global__ __launch_bounds__(128) void k_final(
    const float* __restrict__ cw1, const float* __restrict__ cb1,
    const float* __restrict__ cw2, float* __restrict__ out)
{
    __shared__ float w1s[64 * 128];
    __shared__ float xv[64];
    __shared__ float red0[4], red1[4];
    int tid = threadIdx.x;
    for (int k = tid; k < 2048; k += 128)
        ((float4*)w1s)[k] = ((const float4*)cw1)[k];
    float rcb = cb1[tid];
    float rc0 = cw2[tid * 2 + 0], rc1 = cw2[tid * 2 + 1];
    float s0 = g_score[0] * (1.f / BTv), s1 = g_score[1] * (1.f / BTv);
    float s2 = g_score[2] * (1.f / BTv), s3 = g_score[3] * (1.f / BTv);
    float mu = fmaxf(s0, s1);
    float e0 = expf(s0 - mu), e1 = expf(s1 - mu);
    float bu0 = e0 / (e0 + e1), bu1 = e1 / (e0 + e1);
    float mi = fmaxf(s2, s3);
    float e2 = expf(s2 - mi), e3 = expf(s3 - mi);
    float bi0 = e2 / (e2 + e3), bi1 = e3 / (e2 + e3);
    __syncthreads();
    for (int bb = 0; bb < 16; bb++) {
        int b = blockIdx.x * 16 + bb;
        if (tid < 64) {
            size_t o = (size_t)b * HIDv + tid;
            float hu = bu0 * g_ret[o] + bu1 * g_ret[(size_t)BTv * HIDv + o];
            float hi = bi0 * g_ret[(size_t)2 * BTv * HIDv + o] + bi1 * g_ret[(size_t)3 * BTv * HIDv + o];
            xv[tid] = hu * hi;
        }
        __syncthreads();
        float acc = rcb;
        #pragma unroll
        for (int k = 0; k < 64; k++) acc += xv[k] * w1s[k * 128 + tid];
        float hh = fmaxf(acc, 0.f);
        float l0 = hh * rc0, l1 = hh * rc1;
        #pragma unroll
        for (int m = 16; m; m >>= 1) {
            l0 += __shfl_xor_sync(0xffffffffu, l0, m);
            l1 += __shfl_xor_sync(0xffffffffu, l1, m);
        }
        int w = tid >> 5, ln = tid & 31;
        if (ln == 0) { red0[w] = l0; red1[w] = l1; }
        __syncthreads();
        if (tid == 0) {
            float L0 = red0[0] + red0[1] + red0[2] + red0[3];
            float L1 = red1[0] + red1[1] + red1[2] + red1[3];
            float mm = fmaxf(L0, L1);
            float ea = expf(L0 - mm), eb = expf(L1 - mm);
            float inv = 1.f / (ea + eb);
            out[b * 2 + 0] = ea * inv;
            out[b * 2 + 1] = eb * inv;
        }
        __syncthreads();
    }
}

// -----------------------------------------------------------------------------
extern "C" void kernel_launch(void* const* d_in, const int* in_sizes, int n_in,
                              void* d_out, int out_size)
{
    const float* feats0 = (const float*)d_in[0];
    const float* feats1 = (const float*)d_in[1];
    const float* t0_pw  = (const float*)d_in[2];
    const float* t0_pb  = (const float*)d_in[3];
    const float* t0_w2  = (const float*)d_in[4];
    const float* t0_b2  = (const float*)d_in[5];
    const float* t0_g   = (const float*)d_in[6];
    const float* t0_be  = (const float*)d_in[7];
    const float* t1_pw  = (const float*)d_in[8];
    const float* t1_pb  = (const float*)d_in[9];
    const float* t1_w2  = (const float*)d_in[10];
    const float* t1_b2  = (const float*)d_in[11];
    const float* t1_g   = (const float*)d_in[12];
    const float* t1_be  = (const float*)d_in[13];
    const float* r_vec  = (const float*)d_in[14];
    const float* attn_u = (const float*)d_in[15];
    const float* attn_i = (const float*)d_in[16];
    const float* su_w1  = (const float*)d_in[17];
    const float* su_b1  = (const float*)d_in[18];
    const float* su_w2  = (const float*)d_in[19];
    const float* si_w1  = (const float*)d_in[20];
    const float* si_b1  = (const float*)d_in[21];
    const float* si_w2  = (const float*)d_in[22];
    const float* cw1    = (const float*)d_in[23];
    const float* cb1    = (const float*)d_in[24];
    const float* cw2    = (const float*)d_in[25];
    const int*   idx0   = (const int*)d_in[26];
    const int*   idx1   = (const int*)d_in[27];
    const int*   emi_u  = (const int*)d_in[28];
    const int*   tgt_u  = (const int*)d_in[29];
    const int*   emi_i  = (const int*)d_in[30];
    const int*   tgt_i  = (const int*)d_in[31];

    k_init<<<(NPv * BTv * HIDv + 255) / 256, 256>>>(r_vec);
    k_tower<<<N0v / 32 + N1v / 32, 256>>>(feats0, feats1,
        t0_pw, t0_pb, t0_w2, t0_b2, t0_g, t0_be,
        t1_pw, t1_pb, t1_w2, t1_b2, t1_g, t1_be, idx0, idx1);
    k_mp1<<<NPv * EPM / 8, 256>>>(emi_u, tgt_u, emi_i, tgt_i, attn_u, attn_i);
    k_mp2<<<(NPv * EPM * 8 + 255) / 256, 256>>>(tgt_u, tgt_i);
    k_mp3<<<(NPv * EPM * 16 + 255) / 256, 256>>>(tgt_u, tgt_i);
    dim3 gsem(BTv / 32, NPv);
    k_sem<<<gsem, 128>>>(su_w1, su_b1, su_w2, si_w1, si_b1, si_w2);
    k_final<<<BTv / 16, 128>>>(cw1, cb1, cw2, (float*)d_out);
}

// round 2
// speedup vs baseline: 1.7806x; 1.7806x over previous
#include <cuda_runtime.h>
#include <math.h>

#define N0v 20000
#define N1v 20000
#define NNODE 40000
#define F0v 512
#define HIDv 64
#define EPM 200000
#define BTv 8192
#define NPv 4

// ---------------- scratch (static device globals; no allocation) -------------
__device__ __align__(16) float g_feat[NNODE * HIDv];     // 10.24 MB
__device__ __align__(16) float g_s[NPv * BTv * 8];       // seg sum of exp(e)
__device__ __align__(16) float g_ret[NPv * BTv * HIDv];  // seg sum of exp(e)*eft
__device__ __align__(16) float g_fr[2 * 3 * 64];         // [side][l][k-pair re/im]
__device__ float g_score[4];

// ---------------- init: zero accumulators, compute rotation chain ------------
__global__ void k_init(const float* __restrict__ r_vec) {
    int idx = blockIdx.x * blockDim.x + threadIdx.x;
    if (idx < NPv * BTv * 8) g_s[idx] = 0.f;
    if (idx < NPv * BTv * HIDv) g_ret[idx] = 0.f;
    if (idx < 4) g_score[idx] = 0.f;
    if (idx < 32) {
        int k = idx;
        float rr = r_vec[k * 2 + 0], ri = r_vec[k * 2 + 1];
        float nm = sqrtf(rr * rr + ri * ri);
        float cr = rr / nm, ci = ri / nm;         // rfull[0]=(cr,ci), rfull[1]=(cr,-ci)
        // user etypes {0,1}: fr[2]=(1,0); fr[1]=rfull[1]; fr[0]=fr[1]*rfull[0]
        float u1r = cr,  u1i = -ci;
        float u0r = u1r * cr - u1i * ci;
        float u0i = u1r * ci + u1i * cr;
        g_fr[(0 * 3 + 0) * 64 + 2 * k] = u0r; g_fr[(0 * 3 + 0) * 64 + 2 * k + 1] = u0i;
        g_fr[(0 * 3 + 1) * 64 + 2 * k] = u1r; g_fr[(0 * 3 + 1) * 64 + 2 * k + 1] = u1i;
        g_fr[(0 * 3 + 2) * 64 + 2 * k] = 1.f; g_fr[(0 * 3 + 2) * 64 + 2 * k + 1] = 0.f;
        // item etypes {1,0}: fr[1]=rfull[0]; fr[0]=fr[1]*rfull[1]
        float i1r = cr,  i1i = ci;
        float i0r = i1r * cr - i1i * (-ci);
        float i0i = i1r * (-ci) + i1i * cr;
        g_fr[(1 * 3 + 0) * 64 + 2 * k] = i0r; g_fr[(1 * 3 + 0) * 64 + 2 * k + 1] = i0i;
        g_fr[(1 * 3 + 1) * 64 + 2 * k] = i1r; g_fr[(1 * 3 + 1) * 64 + 2 * k + 1] = i1i;
        g_fr[(1 * 3 + 2) * 64 + 2 * k] = 1.f; g_fr[(1 * 3 + 2) * 64 + 2 * k + 1] = 0.f;
    }
}

// ---------------- towers: Linear(512->64)+GELU+Linear(64->64)+res+LN ---------
// 64 nodes x 64 cols per block, 4x4 per thread, K-chunk 32.
__global__ __launch_bounds__(256) void k_tower(
    const float* __restrict__ feats0, const float* __restrict__ feats1,
    const float* __restrict__ pw0, const float* __restrict__ pb0,
    const float* __restrict__ w20, const float* __restrict__ b20,
    const float* __restrict__ gg0, const float* __restrict__ be0,
    const float* __restrict__ pw1, const float* __restrict__ pb1,
    const float* __restrict__ w21, const float* __restrict__ b21,
    const float* __restrict__ gg1, const float* __restrict__ be1,
    const int* __restrict__ idx0, const int* __restrict__ idx1)
{
    __shared__ __align__(16) float smbuf[4352 + 4096];
    float (*xs)[36] = (float(*)[36])smbuf;            // [64 nodes][32k + pad]
    float (*ws)[64] = (float(*)[64])(smbuf + 2304);   // [32 k][64 cols]
    float (*hs)[68] = (float(*)[68])smbuf;            // [64 nodes][64k + pad]
    float (*w2s)[64] = (float(*)[64])(smbuf + 4352);  // [64 k][64 cols]

    const int NB0 = (N0v + 63) / 64;  // 313
    const int NB1 = (N1v + 63) / 64;  // 313
    int bt = blockIdx.x;
    int tower = (bt >= NB0) ? 1 : 0;
    int bl = tower ? bt - NB0 : bt;
    int nbase = bl * 64;
    int Nlim = tower ? N1v : N0v;
    int valid = Nlim - nbase; if (valid > 64) valid = 64;
    const float* X  = tower ? feats1 : feats0;
    const float* PW = tower ? pw1 : pw0;
    const float* PB = tower ? pb1 : pb0;
    const float* W2 = tower ? w21 : w20;
    const float* B2 = tower ? b21 : b20;
    const float* GG = tower ? gg1 : gg0;
    const float* BE = tower ? be1 : be0;
    const int*  IDX = tower ? idx1 : idx0;

    int tid = threadIdx.x;
    int c4 = (tid & 15) * 4;        // 4 output cols
    int n4 = (tid >> 4) * 4;        // 4 nodes
    int ln = tid >> 2;              // x loader node 0..63
    int lk = (tid & 3) * 8;         // x loader k offset
    int wr = tid >> 3;              // w loader row 0..31
    int wc = (tid & 7) * 8;         // w loader col offset

    int lrow = nbase + ln; if (lrow >= Nlim) lrow = Nlim - 1;

    float acc[4][4];
    #pragma unroll
    for (int j = 0; j < 4; j++)
        #pragma unroll
        for (int c = 0; c < 4; c++) acc[j][c] = 0.f;

    for (int kc = 0; kc < F0v; kc += 32) {
        const float* xr = X + (size_t)lrow * F0v + kc + lk;
        float4 a4 = *(const float4*)xr;
        float4 b4 = *(const float4*)(xr + 4);
        *(float4*)&xs[ln][lk] = a4;
        *(float4*)&xs[ln][lk + 4] = b4;
        const float* wsrc = PW + (size_t)(kc + wr) * HIDv + wc;
        *(float4*)&ws[wr][wc] = *(const float4*)wsrc;
        *(float4*)&ws[wr][wc + 4] = *(const float4*)(wsrc + 4);
        __syncthreads();
        #pragma unroll
        for (int kk = 0; kk < 32; kk += 4) {
            float4 xv[4], wv[4];
            #pragma unroll
            for (int j = 0; j < 4; j++) xv[j] = *(float4*)&xs[n4 + j][kk];
            #pragma unroll
            for (int t = 0; t < 4; t++) wv[t] = *(float4*)&ws[kk + t][c4];
            #pragma unroll
            for (int j = 0; j < 4; j++) {
                acc[j][0] += xv[j].x * wv[0].x; acc[j][1] += xv[j].x * wv[0].y;
                acc[j][2] += xv[j].x * wv[0].z; acc[j][3] += xv[j].x * wv[0].w;
                acc[j][0] += xv[j].y * wv[1].x; acc[j][1] += xv[j].y * wv[1].y;
                acc[j][2] += xv[j].y * wv[1].z; acc[j][3] += xv[j].y * wv[1].w;
                acc[j][0] += xv[j].z * wv[2].x; acc[j][1] += xv[j].z * wv[2].y;
                acc[j][2] += xv[j].z * wv[2].z; acc[j][3] += xv[j].z * wv[2].w;
                acc[j][0] += xv[j].w * wv[3].x; acc[j][1] += xv[j].w * wv[3].y;
                acc[j][2] += xv[j].w * wv[3].z; acc[j][3] += xv[j].w * wv[3].w;
            }
        }
        __syncthreads();
    }

    // z = acc + bias; h = gelu(z) -> hs; load W2
    float z[4][4];
    #pragma unroll
    for (int j = 0; j < 4; j++) {
        float4 hv;
        #pragma unroll
        for (int c = 0; c < 4; c++) z[j][c] = acc[j][c] + PB[c4 + c];
        hv.x = 0.5f * z[j][0] * (1.f + erff(z[j][0] * 0.70710678118654752f));
        hv.y = 0.5f * z[j][1] * (1.f + erff(z[j][1] * 0.70710678118654752f));
        hv.z = 0.5f * z[j][2] * (1.f + erff(z[j][2] * 0.70710678118654752f));
        hv.w = 0.5f * z[j][3] * (1.f + erff(z[j][3] * 0.70710678118654752f));
        *(float4*)&hs[n4 + j][c4] = hv;
    }
    {
        int r = tid >> 2;               // 0..63
        int c = (tid & 3) * 16;
        const float* wsrc = W2 + (size_t)r * HIDv + c;
        *(float4*)&w2s[r][c + 0]  = *(const float4*)(wsrc + 0);
        *(float4*)&w2s[r][c + 4]  = *(const float4*)(wsrc + 4);
        *(float4*)&w2s[r][c + 8]  = *(const float4*)(wsrc + 8);
        *(float4*)&w2s[r][c + 12] = *(const float4*)(wsrc + 12);
    }
    __syncthreads();

    float y[4][4];
    #pragma unroll
    for (int j = 0; j < 4; j++)
        #pragma unroll
        for (int c = 0; c < 4; c++) y[j][c] = 0.f;
    #pragma unroll
    for (int kk = 0; kk < 64; kk += 4) {
        float4 xv[4], wv[4];
        #pragma unroll
        for (int j = 0; j < 4; j++) xv[j] = *(float4*)&hs[n4 + j][kk];
        #pragma unroll
        for (int t = 0; t < 4; t++) wv[t] = *(float4*)&w2s[kk + t][c4];
        #pragma unroll
        for (int j = 0; j < 4; j++) {
            y[j][0] += xv[j].x * wv[0].x; y[j][1] += xv[j].x * wv[0].y;
            y[j][2] += xv[j].x * wv[0].z; y[j][3] += xv[j].x * wv[0].w;
            y[j][0] += xv[j].y * wv[1].x; y[j][1] += xv[j].y * wv[1].y;
            y[j][2] += xv[j].y * wv[1].z; y[j][3] += xv[j].y * wv[1].w;
            y[j][0] += xv[j].z * wv[2].x; y[j][1] += xv[j].z * wv[2].y;
            y[j][2] += xv[j].z * wv[2].z; y[j][3] += xv[j].z * wv[2].w;
            y[j][0] += xv[j].w * wv[3].x; y[j][1] += xv[j].w * wv[3].y;
            y[j][2] += xv[j].w * wv[3].z; y[j][3] += xv[j].w * wv[3].w;
        }
    }
    #pragma unroll
    for (int j = 0; j < 4; j++)
        #pragma unroll
        for (int c = 0; c < 4; c++) y[j][c] += B2[c4 + c] + z[j][c];

    // LayerNorm per node across the 16 threads of the half-warp sharing n4
    #pragma unroll
    for (int j = 0; j < 4; j++) {
        float s1 = y[j][0] + y[j][1] + y[j][2] + y[j][3];
        float s2 = y[j][0]*y[j][0] + y[j][1]*y[j][1] + y[j][2]*y[j][2] + y[j][3]*y[j][3];
        #pragma unroll
        for (int m = 1; m < 16; m <<= 1) {
            s1 += __shfl_xor_sync(0xffffffffu, s1, m);
            s2 += __shfl_xor_sync(0xffffffffu, s2, m);
        }
        float mu = s1 * (1.f / 64.f);
        float rs = 1.f / sqrtf(s2 * (1.f / 64.f) - mu * mu + 1e-5f);
        if (n4 + j < valid) {
            int gn = IDX[nbase + n4 + j];
            float4 o;
            o.x = (y[j][0] - mu) * rs * GG[c4 + 0] + BE[c4 + 0];
            o.y = (y[j][1] - mu) * rs * GG[c4 + 1] + BE[c4 + 1];
            o.z = (y[j][2] - mu) * rs * GG[c4 + 2] + BE[c4 + 2];
            o.w = (y[j][3] - mu) * rs * GG[c4 + 3] + BE[c4 + 3];
            *(float4*)&g_feat[(size_t)gn * HIDv + c4] = o;
        }
    }
}

// ---- fused metapath: gather+rotate+mean -> e -> exp -> seg sums (no max) ----
// 16 lanes per instance; 2 instances per warp.
__global__ __launch_bounds__(256) void k_mpf(
    const int* __restrict__ emi_u, const int* __restrict__ tgt_u,
    const int* __restrict__ emi_i, const int* __restrict__ tgt_i,
    const float* __restrict__ attn_u, const float* __restrict__ attn_i)
{
    int warp = blockIdx.x * (blockDim.x >> 5) + (threadIdx.x >> 5);
    int lane = threadIdx.x & 31;
    int half = lane >> 4;
    int sl = lane & 15;
    int inst = warp * 2 + half;            // 0 .. 799999
    int p = inst / EPM;
    int i = inst - p * EPM;
    int side = p >> 1, pl = p & 1;
    const int* emi = side ? emi_i : emi_u;
    const int* tgt = side ? tgt_i : tgt_u;
    const float* attn = side ? attn_i : attn_u;

    int n = 0;
    if (sl < 3) n = emi[((size_t)pl * EPM + i) * 3 + sl];
    float re0 = 0.f, im0 = 0.f, re1 = 0.f, im1 = 0.f;
    #pragma unroll
    for (int l = 0; l < 3; l++) {
        int nl = __shfl_sync(0xffffffffu, n, half * 16 + l);
        float4 v  = *(const float4*)&g_feat[(size_t)nl * HIDv + sl * 4];
        float4 fr = *(const float4*)&g_fr[(side * 3 + l) * 64 + sl * 4];
        re0 += v.x * fr.x - v.y * fr.y;
        im0 += v.x * fr.y + v.y * fr.x;
        re1 += v.z * fr.z - v.w * fr.w;
        im1 += v.z * fr.w + v.w * fr.z;
    }
    re0 *= (1.f / 3.f); im0 *= (1.f / 3.f);
    re1 *= (1.f / 3.f); im1 *= (1.f / 3.f);

    int h = sl >> 1;
    int dpart = (sl & 1) * 4;
    float4 av = *(const float4*)&attn[(pl * 8 + h) * 8 + dpart];
    float ep = re0 * av.x + im0 * av.y + re1 * av.z + im1 * av.w;
    ep += __shfl_xor_sync(0xffffffffu, ep, 1);
    float ev = ep > 0.f ? ep : 0.01f * ep;    // leaky_relu
    float a = expf(ev);                       // safe: |e| small, no max needed

    int t = tgt[(size_t)pl * EPM + i];
    size_t seg = (size_t)p * BTv + t;
    if ((sl & 1) == 0) atomicAdd(&g_s[seg * 8 + h], a);
    atomicAdd((float4*)&g_ret[seg * HIDv + sl * 4],
              make_float4(a * re0, a * im0, a * re1, a * im1));
}

// ---------------- normalize + elu + semantic attention scores ----------------
__global__ __launch_bounds__(128) void k_sem(
    const float* __restrict__ su_w1, const float* __restrict__ su_b1, const float* __restrict__ su_w2,
    const float* __restrict__ si_w1, const float* __restrict__ si_b1, const float* __restrict__ si_w2)
{
    __shared__ float w1s[64 * 128];
    __shared__ float v[64];
    __shared__ float red[4];
    int p = blockIdx.y;
    const float* w1 = (p < 2) ? su_w1 : si_w1;
    const float* b1 = (p < 2) ? su_b1 : si_b1;
    const float* w2 = (p < 2) ? su_w2 : si_w2;
    int tid = threadIdx.x;
    for (int k = tid; k < 2048; k += 128)
        ((float4*)w1s)[k] = ((const float4*)w1)[k];
    float rb1 = b1[tid], rw2 = w2[tid];
    float lsum = 0.f;
    __syncthreads();
    for (int bb = 0; bb < 32; bb++) {
        int b = blockIdx.x * 32 + bb;
        if (tid < 64) {
            size_t off = ((size_t)p * BTv + b) * HIDv + tid;
            float sd = g_s[((size_t)p * BTv + b) * 8 + (tid >> 3)];
            float x = g_ret[off] / (sd + 1e-9f);
            float el = x > 0.f ? x : expf(x) - 1.f;   // elu
            g_ret[off] = el;                          // persist for final stage
            v[tid] = el;
        }
        __syncthreads();
        float acc = rb1;
        #pragma unroll
        for (int k = 0; k < 64; k++) acc += v[k] * w1s[k * 128 + tid];
        lsum += tanhf(acc) * rw2;
        __syncthreads();
    }
    #pragma unroll
    for (int m = 16; m; m >>= 1) lsum += __shfl_xor_sync(0xffffffffu, lsum, m);
    int w = tid >> 5, lnn = tid & 31;
    if (lnn == 0) red[w] = lsum;
    __syncthreads();
    if (tid == 0) atomicAdd(&g_score[p], red[0] + red[1] + red[2] + red[3]);
}

// ---------------- beta softmax, fuse sides, ProductMLP, softmax --------------
__global__ __launch_bounds__(128) void k_final(
    const float* __restrict__ cw1, const float* __restrict__ cb1,
    const float* __restrict__ cw2, float* __restrict__ out)
{
    __shared__ float w1s[64 * 128];
    __shared__ float xv[64];
    __shared__ float red0[4], red1[4];
    int tid = threadIdx.x;
    for (int k = tid; k < 2048; k += 128)
        ((float4*)w1s)[k] = ((const float4*)cw1)[k];
    float rcb = cb1[tid];
    float rc0 = cw2[tid * 2 + 0], rc1 = cw2[tid * 2 + 1];
    float s0 = g_score[0] * (1.f / BTv), s1 = g_score[1] * (1.f / BTv);
    float s2 = g_score[2] * (1.f / BTv), s3 = g_score[3] * (1.f / BTv);
    float mu = fmaxf(s0, s1);
    float e0 = expf(s0 - mu), e1 = expf(s1 - mu);
    float bu0 = e0 / (e0 + e1), bu1 = e1 / (e0 + e1);
    float mi = fmaxf(s2, s3);
    float e2 = expf(s2 - mi), e3 = expf(s3 - mi);
    float bi0 = e2 / (e2 + e3), bi1 = e3 / (e2 + e3);
    __syncthreads();
    for (int bb = 0; bb < 16; bb++) {
        int b = blockIdx.x * 16 + bb;
        if (tid < 64) {
            size_t o = (size_t)b * HIDv + tid;
            float hu = bu0 * g_ret[o] + bu1 * g_ret[(size_t)BTv * HIDv + o];
            float hi = bi0 * g_ret[(size_t)2 * BTv * HIDv + o] + bi1 * g_ret[(size_t)3 * BTv * HIDv + o];
            xv[tid] = hu * hi;
        }
        __syncthreads();
        float acc = rcb;
        #pragma unroll
        for (int k = 0; k < 64; k++) acc += xv[k] * w1s[k * 128 + tid];
        float hh = fmaxf(acc, 0.f);
        float l0 = hh * rc0, l1 = hh * rc1;
        #pragma unroll
        for (int m = 16; m; m >>= 1) {
            l0 += __shfl_xor_sync(0xffffffffu, l0, m);
            l1 += __shfl_xor_sync(0xffffffffu, l1, m);
        }
        int w = tid >> 5, lnn = tid & 31;
        if (lnn == 0) { red0[w] = l0; red1[w] = l1; }
        __syncthreads();
        if (tid == 0) {
            float L0 = red0[0] + red0[1] + red0[2] + red0[3];
            float L1 = red1[0] + red1[1] + red1[2] + red1[3];
            float mm = fmaxf(L0, L1);
            float ea = expf(L0 - mm), eb = expf(L1 - mm);
            float inv = 1.f / (ea + eb);
            out[b * 2 + 0] = ea * inv;
            out[b * 2 + 1] = eb * inv;
        }
        __syncthreads();
    }
}

// -----------------------------------------------------------------------------
extern "C" void kernel_launch(void* const* d_in, const int* in_sizes, int n_in,
                              void* d_out, int out_size)
{
    const float* feats0 = (const float*)d_in[0];
    const float* feats1 = (const float*)d_in[1];
    const float* t0_pw  = (const float*)d_in[2];
    const float* t0_pb  = (const float*)d_in[3];
    const float* t0_w2  = (const float*)d_in[4];
    const float* t0_b2  = (const float*)d_in[5];
    const float* t0_g   = (const float*)d_in[6];
    const float* t0_be  = (const float*)d_in[7];
    const float* t1_pw  = (const float*)d_in[8];
    const float* t1_pb  = (const float*)d_in[9];
    const float* t1_w2  = (const float*)d_in[10];
    const float* t1_b2  = (const float*)d_in[11];
    const float* t1_g   = (const float*)d_in[12];
    const float* t1_be  = (const float*)d_in[13];
    const float* r_vec  = (const float*)d_in[14];
    const float* attn_u = (const float*)d_in[15];
    const float* attn_i = (const float*)d_in[16];
    const float* su_w1  = (const float*)d_in[17];
    const float* su_b1  = (const float*)d_in[18];
    const float* su_w2  = (const float*)d_in[19];
    const float* si_w1  = (const float*)d_in[20];
    const float* si_b1  = (const float*)d_in[21];
    const float* si_w2  = (const float*)d_in[22];
    const float* cw1    = (const float*)d_in[23];
    const float* cb1    = (const float*)d_in[24];
    const float* cw2    = (const float*)d_in[25];
    const int*   idx0   = (const int*)d_in[26];
    const int*   idx1   = (const int*)d_in[27];
    const int*   emi_u  = (const int*)d_in[28];
    const int*   tgt_u  = (const int*)d_in[29];
    const int*   emi_i  = (const int*)d_in[30];
    const int*   tgt_i  = (const int*)d_in[31];

    k_init<<<(NPv * BTv * HIDv + 255) / 256, 256>>>(r_vec);
    k_tower<<<(N0v + 63) / 64 + (N1v + 63) / 64, 256>>>(feats0, feats1,
        t0_pw, t0_pb, t0_w2, t0_b2, t0_g, t0_be,
        t1_pw, t1_pb, t1_w2, t1_b2, t1_g, t1_be, idx0, idx1);
    k_mpf<<<NPv * EPM / 16, 256>>>(emi_u, tgt_u, emi_i, tgt_i, attn_u, attn_i);
    dim3 gsem(BTv / 32, NPv);
    k_sem<<<gsem, 128>>>(su_w1, su_b1, su_w2, si_w1, si_b1, si_w2);
    k_final<<<BTv / 16, 128>>>(cw1, cb1, cw2, (float*)d_out);
}

// round 3
// speedup vs baseline: 2.1688x; 1.2180x over previous
#include <cuda_runtime.h>
#include <math.h>

#define N0v 20000
#define N1v 20000
#define NNODE 40000
#define F0v 512
#define HIDv 64
#define EPM 200000
#define BTv 8192
#define NPv 4

// ---------------- scratch (static device globals; no allocation) -------------
__device__ __align__(16) float g_feat[NNODE * HIDv];     // 10.24 MB
__device__ __align__(16) float g_s[NPv * BTv * 8];       // seg sum of exp(e)
__device__ __align__(16) float g_ret[NPv * BTv * HIDv];  // seg sum of exp(e)*eft
__device__ __align__(16) float g_fr[2 * 3 * 64];         // [side][l][k-pair re/im]
__device__ float g_score[4];

// ---------------- init: zero accumulators, compute rotation chain ------------
__global__ void k_init(const float* __restrict__ r_vec) {
    int idx = blockIdx.x * blockDim.x + threadIdx.x;
    if (idx < NPv * BTv * 8) g_s[idx] = 0.f;
    if (idx < NPv * BTv * HIDv) g_ret[idx] = 0.f;
    if (idx < 4) g_score[idx] = 0.f;
    if (idx < 32) {
        int k = idx;
        float rr = r_vec[k * 2 + 0], ri = r_vec[k * 2 + 1];
        float nm = sqrtf(rr * rr + ri * ri);
        float cr = rr / nm, ci = ri / nm;         // rfull[0]=(cr,ci), rfull[1]=(cr,-ci)
        float u1r = cr,  u1i = -ci;
        float u0r = u1r * cr - u1i * ci;
        float u0i = u1r * ci + u1i * cr;
        g_fr[(0 * 3 + 0) * 64 + 2 * k] = u0r; g_fr[(0 * 3 + 0) * 64 + 2 * k + 1] = u0i;
        g_fr[(0 * 3 + 1) * 64 + 2 * k] = u1r; g_fr[(0 * 3 + 1) * 64 + 2 * k + 1] = u1i;
        g_fr[(0 * 3 + 2) * 64 + 2 * k] = 1.f; g_fr[(0 * 3 + 2) * 64 + 2 * k + 1] = 0.f;
        float i1r = cr,  i1i = ci;
        float i0r = i1r * cr - i1i * (-ci);
        float i0i = i1r * (-ci) + i1i * cr;
        g_fr[(1 * 3 + 0) * 64 + 2 * k] = i0r; g_fr[(1 * 3 + 0) * 64 + 2 * k + 1] = i0i;
        g_fr[(1 * 3 + 1) * 64 + 2 * k] = i1r; g_fr[(1 * 3 + 1) * 64 + 2 * k + 1] = i1i;
        g_fr[(1 * 3 + 2) * 64 + 2 * k] = 1.f; g_fr[(1 * 3 + 2) * 64 + 2 * k + 1] = 0.f;
    }
}

// ---------------- towers: Linear(512->64)+GELU+Linear(64->64)+res+LN ---------
__global__ __launch_bounds__(256) void k_tower(
    const float* __restrict__ feats0, const float* __restrict__ feats1,
    const float* __restrict__ pw0, const float* __restrict__ pb0,
    const float* __restrict__ w20, const float* __restrict__ b20,
    const float* __restrict__ gg0, const float* __restrict__ be0,
    const float* __restrict__ pw1, const float* __restrict__ pb1,
    const float* __restrict__ w21, const float* __restrict__ b21,
    const float* __restrict__ gg1, const float* __restrict__ be1,
    const int* __restrict__ idx0, const int* __restrict__ idx1)
{
    __shared__ __align__(16) float smbuf[4352 + 4096];
    float (*xs)[36] = (float(*)[36])smbuf;            // [64 nodes][32k + pad]
    float (*ws)[64] = (float(*)[64])(smbuf + 2304);   // [32 k][64 cols]
    float (*hs)[68] = (float(*)[68])smbuf;            // [64 nodes][64k + pad]
    float (*w2s)[64] = (float(*)[64])(smbuf + 4352);  // [64 k][64 cols]

    const int NB0 = (N0v + 63) / 64;
    int bt = blockIdx.x;
    int tower = (bt >= NB0) ? 1 : 0;
    int bl = tower ? bt - NB0 : bt;
    int nbase = bl * 64;
    int Nlim = tower ? N1v : N0v;
    int valid = Nlim - nbase; if (valid > 64) valid = 64;
    const float* X  = tower ? feats1 : feats0;
    const float* PW = tower ? pw1 : pw0;
    const float* PB = tower ? pb1 : pb0;
    const float* W2 = tower ? w21 : w20;
    const float* B2 = tower ? b21 : b20;
    const float* GG = tower ? gg1 : gg0;
    const float* BE = tower ? be1 : be0;
    const int*  IDX = tower ? idx1 : idx0;

    int tid = threadIdx.x;
    int c4 = (tid & 15) * 4;
    int n4 = (tid >> 4) * 4;
    int ln = tid >> 2;
    int lk = (tid & 3) * 8;
    int wr = tid >> 3;
    int wc = (tid & 7) * 8;

    int lrow = nbase + ln; if (lrow >= Nlim) lrow = Nlim - 1;

    float acc[4][4];
    #pragma unroll
    for (int j = 0; j < 4; j++)
        #pragma unroll
        for (int c = 0; c < 4; c++) acc[j][c] = 0.f;

    for (int kc = 0; kc < F0v; kc += 32) {
        const float* xr = X + (size_t)lrow * F0v + kc + lk;
        float4 a4 = *(const float4*)xr;
        float4 b4 = *(const float4*)(xr + 4);
        *(float4*)&xs[ln][lk] = a4;
        *(float4*)&xs[ln][lk + 4] = b4;
        const float* wsrc = PW + (size_t)(kc + wr) * HIDv + wc;
        *(float4*)&ws[wr][wc] = *(const float4*)wsrc;
        *(float4*)&ws[wr][wc + 4] = *(const float4*)(wsrc + 4);
        __syncthreads();
        #pragma unroll
        for (int kk = 0; kk < 32; kk += 4) {
            float4 xv[4], wv[4];
            #pragma unroll
            for (int j = 0; j < 4; j++) xv[j] = *(float4*)&xs[n4 + j][kk];
            #pragma unroll
            for (int t = 0; t < 4; t++) wv[t] = *(float4*)&ws[kk + t][c4];
            #pragma unroll
            for (int j = 0; j < 4; j++) {
                acc[j][0] += xv[j].x * wv[0].x; acc[j][1] += xv[j].x * wv[0].y;
                acc[j][2] += xv[j].x * wv[0].z; acc[j][3] += xv[j].x * wv[0].w;
                acc[j][0] += xv[j].y * wv[1].x; acc[j][1] += xv[j].y * wv[1].y;
                acc[j][2] += xv[j].y * wv[1].z; acc[j][3] += xv[j].y * wv[1].w;
                acc[j][0] += xv[j].z * wv[2].x; acc[j][1] += xv[j].z * wv[2].y;
                acc[j][2] += xv[j].z * wv[2].z; acc[j][3] += xv[j].z * wv[2].w;
                acc[j][0] += xv[j].w * wv[3].x; acc[j][1] += xv[j].w * wv[3].y;
                acc[j][2] += xv[j].w * wv[3].z; acc[j][3] += xv[j].w * wv[3].w;
            }
        }
        __syncthreads();
    }

    float z[4][4];
    #pragma unroll
    for (int j = 0; j < 4; j++) {
        float4 hv;
        #pragma unroll
        for (int c = 0; c < 4; c++) z[j][c] = acc[j][c] + PB[c4 + c];
        hv.x = 0.5f * z[j][0] * (1.f + erff(z[j][0] * 0.70710678118654752f));
        hv.y = 0.5f * z[j][1] * (1.f + erff(z[j][1] * 0.70710678118654752f));
        hv.z = 0.5f * z[j][2] * (1.f + erff(z[j][2] * 0.70710678118654752f));
        hv.w = 0.5f * z[j][3] * (1.f + erff(z[j][3] * 0.70710678118654752f));
        *(float4*)&hs[n4 + j][c4] = hv;
    }
    {
        int r = tid >> 2;
        int c = (tid & 3) * 16;
        const float* wsrc = W2 + (size_t)r * HIDv + c;
        *(float4*)&w2s[r][c + 0]  = *(const float4*)(wsrc + 0);
        *(float4*)&w2s[r][c + 4]  = *(const float4*)(wsrc + 4);
        *(float4*)&w2s[r][c + 8]  = *(const float4*)(wsrc + 8);
        *(float4*)&w2s[r][c + 12] = *(const float4*)(wsrc + 12);
    }
    __syncthreads();

    float y[4][4];
    #pragma unroll
    for (int j = 0; j < 4; j++)
        #pragma unroll
        for (int c = 0; c < 4; c++) y[j][c] = 0.f;
    #pragma unroll
    for (int kk = 0; kk < 64; kk += 4) {
        float4 xv[4], wv[4];
        #pragma unroll
        for (int j = 0; j < 4; j++) xv[j] = *(float4*)&hs[n4 + j][kk];
        #pragma unroll
        for (int t = 0; t < 4; t++) wv[t] = *(float4*)&w2s[kk + t][c4];
        #pragma unroll
        for (int j = 0; j < 4; j++) {
            y[j][0] += xv[j].x * wv[0].x; y[j][1] += xv[j].x * wv[0].y;
            y[j][2] += xv[j].x * wv[0].z; y[j][3] += xv[j].x * wv[0].w;
            y[j][0] += xv[j].y * wv[1].x; y[j][1] += xv[j].y * wv[1].y;
            y[j][2] += xv[j].y * wv[1].z; y[j][3] += xv[j].y * wv[1].w;
            y[j][0] += xv[j].z * wv[2].x; y[j][1] += xv[j].z * wv[2].y;
            y[j][2] += xv[j].z * wv[2].z; y[j][3] += xv[j].z * wv[2].w;
            y[j][0] += xv[j].w * wv[3].x; y[j][1] += xv[j].w * wv[3].y;
            y[j][2] += xv[j].w * wv[3].z; y[j][3] += xv[j].w * wv[3].w;
        }
    }
    #pragma unroll
    for (int j = 0; j < 4; j++)
        #pragma unroll
        for (int c = 0; c < 4; c++) y[j][c] += B2[c4 + c] + z[j][c];

    #pragma unroll
    for (int j = 0; j < 4; j++) {
        float s1 = y[j][0] + y[j][1] + y[j][2] + y[j][3];
        float s2 = y[j][0]*y[j][0] + y[j][1]*y[j][1] + y[j][2]*y[j][2] + y[j][3]*y[j][3];
        #pragma unroll
        for (int m = 1; m < 16; m <<= 1) {
            s1 += __shfl_xor_sync(0xffffffffu, s1, m);
            s2 += __shfl_xor_sync(0xffffffffu, s2, m);
        }
        float mu = s1 * (1.f / 64.f);
        float rs = 1.f / sqrtf(s2 * (1.f / 64.f) - mu * mu + 1e-5f);
        if (n4 + j < valid) {
            int gn = IDX[nbase + n4 + j];
            float4 o;
            o.x = (y[j][0] - mu) * rs * GG[c4 + 0] + BE[c4 + 0];
            o.y = (y[j][1] - mu) * rs * GG[c4 + 1] + BE[c4 + 1];
            o.z = (y[j][2] - mu) * rs * GG[c4 + 2] + BE[c4 + 2];
            o.w = (y[j][3] - mu) * rs * GG[c4 + 3] + BE[c4 + 3];
            *(float4*)&g_feat[(size_t)gn * HIDv + c4] = o;
        }
    }
}

// ---- fused metapath: gather+rotate+mean -> e -> exp -> seg sums (no max) ----
__global__ __launch_bounds__(256) void k_mpf(
    const int* __restrict__ emi_u, const int* __restrict__ tgt_u,
    const int* __restrict__ emi_i, const int* __restrict__ tgt_i,
    const float* __restrict__ attn_u, const float* __restrict__ attn_i)
{
    int warp = blockIdx.x * (blockDim.x >> 5) + (threadIdx.x >> 5);
    int lane = threadIdx.x & 31;
    int half = lane >> 4;
    int sl = lane & 15;
    int inst = warp * 2 + half;
    int p = inst / EPM;
    int i = inst - p * EPM;
    int side = p >> 1, pl = p & 1;
    const int* emi = side ? emi_i : emi_u;
    const int* tgt = side ? tgt_i : tgt_u;
    const float* attn = side ? attn_i : attn_u;

    int n = 0;
    if (sl < 3) n = emi[((size_t)pl * EPM + i) * 3 + sl];
    float re0 = 0.f, im0 = 0.f, re1 = 0.f, im1 = 0.f;
    #pragma unroll
    for (int l = 0; l < 3; l++) {
        int nl = __shfl_sync(0xffffffffu, n, half * 16 + l);
        float4 v  = *(const float4*)&g_feat[(size_t)nl * HIDv + sl * 4];
        float4 fr = *(const float4*)&g_fr[(side * 3 + l) * 64 + sl * 4];
        re0 += v.x * fr.x - v.y * fr.y;
        im0 += v.x * fr.y + v.y * fr.x;
        re1 += v.z * fr.z - v.w * fr.w;
        im1 += v.z * fr.w + v.w * fr.z;
    }
    re0 *= (1.f / 3.f); im0 *= (1.f / 3.f);
    re1 *= (1.f / 3.f); im1 *= (1.f / 3.f);

    int h = sl >> 1;
    int dpart = (sl & 1) * 4;
    float4 av = *(const float4*)&attn[(pl * 8 + h) * 8 + dpart];
    float ep = re0 * av.x + im0 * av.y + re1 * av.z + im1 * av.w;
    ep += __shfl_xor_sync(0xffffffffu, ep, 1);
    float ev = ep > 0.f ? ep : 0.01f * ep;
    float a = expf(ev);

    int t = tgt[(size_t)pl * EPM + i];
    size_t seg = (size_t)p * BTv + t;
    if ((sl & 1) == 0) atomicAdd(&g_s[seg * 8 + h], a);
    atomicAdd((float4*)&g_ret[seg * HIDv + sl * 4],
              make_float4(a * re0, a * im0, a * re1, a * im1));
}

// -------- semantic: normalize+elu (persist), GEMM [64x128], tanh, dot w2 -----
// grid (BTv/64, NPv), 256 threads. Each thread: 4 rows x 8 cols.
__global__ __launch_bounds__(256) void k_sem(
    const float* __restrict__ su_w1, const float* __restrict__ su_b1, const float* __restrict__ su_w2,
    const float* __restrict__ si_w1, const float* __restrict__ si_b1, const float* __restrict__ si_w2)
{
    __shared__ __align__(16) float vs[64][68];
    __shared__ __align__(16) float w1s[64 * 128];
    __shared__ float red[8];
    int p = blockIdx.y;
    const float* w1 = (p < 2) ? su_w1 : si_w1;
    const float* b1 = (p < 2) ? su_b1 : si_b1;
    const float* w2 = (p < 2) ? su_w2 : si_w2;
    int tid = threadIdx.x;

    for (int k = tid; k < 2048; k += 256)
        ((float4*)w1s)[k] = ((const float4*)w1)[k];

    // loader: row = tid>>2 (0..63), 4 float4 cols; normalize + elu + persist
    {
        int row = tid >> 2;
        int b_g = blockIdx.x * 64 + row;
        size_t seg = (size_t)p * BTv + b_g;
        #pragma unroll
        for (int cc = 0; cc < 4; cc++) {
            int c0 = (tid & 3) * 16 + cc * 4;
            float sd = g_s[seg * 8 + (c0 >> 3)] + 1e-9f;
            float inv = 1.f / sd;
            float4 v = *(const float4*)&g_ret[seg * HIDv + c0];
            v.x *= inv; v.y *= inv; v.z *= inv; v.w *= inv;
            v.x = v.x > 0.f ? v.x : expf(v.x) - 1.f;
            v.y = v.y > 0.f ? v.y : expf(v.y) - 1.f;
            v.z = v.z > 0.f ? v.z : expf(v.z) - 1.f;
            v.w = v.w > 0.f ? v.w : expf(v.w) - 1.f;
            *(float4*)&g_ret[seg * HIDv + c0] = v;    // persist for k_final
            *(float4*)&vs[row][c0] = v;
        }
    }
    __syncthreads();

    int n4 = (tid >> 4) * 4;
    int c8 = (tid & 15) * 8;
    float acc[4][8];
    #pragma unroll
    for (int j = 0; j < 4; j++)
        #pragma unroll
        for (int c = 0; c < 8; c++) acc[j][c] = 0.f;

    #pragma unroll
    for (int kk = 0; kk < 64; kk += 4) {
        float4 xv[4];
        #pragma unroll
        for (int j = 0; j < 4; j++) xv[j] = *(float4*)&vs[n4 + j][kk];
        #pragma unroll
        for (int t = 0; t < 4; t++) {
            float4 wa = *(float4*)&w1s[(kk + t) * 128 + c8];
            float4 wb = *(float4*)&w1s[(kk + t) * 128 + c8 + 4];
            #pragma unroll
            for (int j = 0; j < 4; j++) {
                float x = (t == 0) ? xv[j].x : (t == 1) ? xv[j].y : (t == 2) ? xv[j].z : xv[j].w;
                acc[j][0] += x * wa.x; acc[j][1] += x * wa.y;
                acc[j][2] += x * wa.z; acc[j][3] += x * wa.w;
                acc[j][4] += x * wb.x; acc[j][5] += x * wb.y;
                acc[j][6] += x * wb.z; acc[j][7] += x * wb.w;
            }
        }
    }

    float lsum = 0.f;
    #pragma unroll
    for (int c = 0; c < 8; c++) {
        float bb = b1[c8 + c];
        float ww = w2[c8 + c];
        #pragma unroll
        for (int j = 0; j < 4; j++)
            lsum += tanhf(acc[j][c] + bb) * ww;
    }
    #pragma unroll
    for (int m = 16; m; m >>= 1) lsum += __shfl_xor_sync(0xffffffffu, lsum, m);
    if ((tid & 31) == 0) red[tid >> 5] = lsum;
    __syncthreads();
    if (tid == 0) {
        float s = 0.f;
        #pragma unroll
        for (int w = 0; w < 8; w++) s += red[w];
        atomicAdd(&g_score[p], s);
    }
}

// -------- final: beta-combine, product, GEMM [64x128], relu, w2, softmax -----
// grid BTv/64, 256 threads, 4 rows x 8 cols per thread.
__global__ __launch_bounds__(256) void k_final(
    const float* __restrict__ cw1, const float* __restrict__ cb1,
    const float* __restrict__ cw2, float* __restrict__ out)
{
    __shared__ __align__(16) float vs[64][68];
    __shared__ __align__(16) float w1s[64 * 128];
    int tid = threadIdx.x;

    for (int k = tid; k < 2048; k += 256)
        ((float4*)w1s)[k] = ((const float4*)cw1)[k];

    float s0 = g_score[0] * (1.f / BTv), s1 = g_score[1] * (1.f / BTv);
    float s2 = g_score[2] * (1.f / BTv), s3 = g_score[3] * (1.f / BTv);
    float mu = fmaxf(s0, s1);
    float e0 = expf(s0 - mu), e1 = expf(s1 - mu);
    float bu0 = e0 / (e0 + e1), bu1 = e1 / (e0 + e1);
    float mi = fmaxf(s2, s3);
    float e2 = expf(s2 - mi), e3 = expf(s3 - mi);
    float bi0 = e2 / (e2 + e3), bi1 = e3 / (e2 + e3);

    {
        int row = tid >> 2;
        int b_g = blockIdx.x * 64 + row;
        size_t o = (size_t)b_g * HIDv;
        #pragma unroll
        for (int cc = 0; cc < 4; cc++) {
            int c0 = (tid & 3) * 16 + cc * 4;
            float4 r0 = *(const float4*)&g_ret[o + c0];
            float4 r1 = *(const float4*)&g_ret[(size_t)BTv * HIDv + o + c0];
            float4 r2 = *(const float4*)&g_ret[(size_t)2 * BTv * HIDv + o + c0];
            float4 r3 = *(const float4*)&g_ret[(size_t)3 * BTv * HIDv + o + c0];
            float4 v;
            v.x = (bu0 * r0.x + bu1 * r1.x) * (bi0 * r2.x + bi1 * r3.x);
            v.y = (bu0 * r0.y + bu1 * r1.y) * (bi0 * r2.y + bi1 * r3.y);
            v.z = (bu0 * r0.z + bu1 * r1.z) * (bi0 * r2.z + bi1 * r3.z);
            v.w = (bu0 * r0.w + bu1 * r1.w) * (bi0 * r2.w + bi1 * r3.w);
            *(float4*)&vs[row][c0] = v;
        }
    }
    __syncthreads();

    int n4 = (tid >> 4) * 4;
    int c8 = (tid & 15) * 8;
    float acc[4][8];
    #pragma unroll
    for (int j = 0; j < 4; j++)
        #pragma unroll
        for (int c = 0; c < 8; c++) acc[j][c] = 0.f;

    #pragma unroll
    for (int kk = 0; kk < 64; kk += 4) {
        float4 xv[4];
        #pragma unroll
        for (int j = 0; j < 4; j++) xv[j] = *(float4*)&vs[n4 + j][kk];
        #pragma unroll
        for (int t = 0; t < 4; t++) {
            float4 wa = *(float4*)&w1s[(kk + t) * 128 + c8];
            float4 wb = *(float4*)&w1s[(kk + t) * 128 + c8 + 4];
            #pragma unroll
            for (int j = 0; j < 4; j++) {
                float x = (t == 0) ? xv[j].x : (t == 1) ? xv[j].y : (t == 2) ? xv[j].z : xv[j].w;
                acc[j][0] += x * wa.x; acc[j][1] += x * wa.y;
                acc[j][2] += x * wa.z; acc[j][3] += x * wa.w;
                acc[j][4] += x * wb.x; acc[j][5] += x * wb.y;
                acc[j][6] += x * wb.z; acc[j][7] += x * wb.w;
            }
        }
    }

    float l0[4] = {0.f,0.f,0.f,0.f}, l1[4] = {0.f,0.f,0.f,0.f};
    #pragma unroll
    for (int c = 0; c < 8; c++) {
        float bb = cb1[c8 + c];
        float wa = cw2[(c8 + c) * 2 + 0];
        float wb = cw2[(c8 + c) * 2 + 1];
        #pragma unroll
        for (int j = 0; j < 4; j++) {
            float hh = fmaxf(acc[j][c] + bb, 0.f);
            l0[j] += hh * wa;
            l1[j] += hh * wb;
        }
    }
    #pragma unroll
    for (int j = 0; j < 4; j++) {
        #pragma unroll
        for (int m = 1; m < 16; m <<= 1) {
            l0[j] += __shfl_xor_sync(0xffffffffu, l0[j], m);
            l1[j] += __shfl_xor_sync(0xffffffffu, l1[j], m);
        }
    }
    if ((tid & 15) == 0) {
        #pragma unroll
        for (int j = 0; j < 4; j++) {
            int b = blockIdx.x * 64 + n4 + j;
            float mm = fmaxf(l0[j], l1[j]);
            float ea = expf(l0[j] - mm), eb = expf(l1[j] - mm);
            float inv = 1.f / (ea + eb);
            out[b * 2 + 0] = ea * inv;
            out[b * 2 + 1] = eb * inv;
        }
    }
}

// -----------------------------------------------------------------------------
extern "C" void kernel_launch(void* const* d_in, const int* in_sizes, int n_in,
                              void* d_out, int out_size)
{
    const float* feats0 = (const float*)d_in[0];
    const float* feats1 = (const float*)d_in[1];
    const float* t0_pw  = (const float*)d_in[2];
    const float* t0_pb  = (const float*)d_in[3];
    const float* t0_w2  = (const float*)d_in[4];
    const float* t0_b2  = (const float*)d_in[5];
    const float* t0_g   = (const float*)d_in[6];
    const float* t0_be  = (const float*)d_in[7];
    const float* t1_pw  = (const float*)d_in[8];
    const float* t1_pb  = (const float*)d_in[9];
    const float* t1_w2  = (const float*)d_in[10];
    const float* t1_b2  = (const float*)d_in[11];
    const float* t1_g   = (const float*)d_in[12];
    const float* t1_be  = (const float*)d_in[13];
    const float* r_vec  = (const float*)d_in[14];
    const float* attn_u = (const float*)d_in[15];
    const float* attn_i = (const float*)d_in[16];
    const float* su_w1  = (const float*)d_in[17];
    const float* su_b1  = (const float*)d_in[18];
    const float* su_w2  = (const float*)d_in[19];
    const float* si_w1  = (const float*)d_in[20];
    const float* si_b1  = (const float*)d_in[21];
    const float* si_w2  = (const float*)d_in[22];
    const float* cw1    = (const float*)d_in[23];
    const float* cb1    = (const float*)d_in[24];
    const float* cw2    = (const float*)d_in[25];
    const int*   idx0   = (const int*)d_in[26];
    const int*   idx1   = (const int*)d_in[27];
    const int*   emi_u  = (const int*)d_in[28];
    const int*   tgt_u  = (const int*)d_in[29];
    const int*   emi_i  = (const int*)d_in[30];
    const int*   tgt_i  = (const int*)d_in[31];

    k_init<<<(NPv * BTv * HIDv + 255) / 256, 256>>>(r_vec);
    k_tower<<<(N0v + 63) / 64 + (N1v + 63) / 64, 256>>>(feats0, feats1,
        t0_pw, t0_pb, t0_w2, t0_b2, t0_g, t0_be,
        t1_pw, t1_pb, t1_w2, t1_b2, t1_g, t1_be, idx0, idx1);
    k_mpf<<<NPv * EPM / 16, 256>>>(emi_u, tgt_u, emi_i, tgt_i, attn_u, attn_i);
    dim3 gsem(BTv / 64, NPv);
    k_sem<<<gsem, 256>>>(su_w1, su_b1, su_w2, si_w1, si_b1, si_w2);
    k_final<<<BTv / 64, 256>>>(cw1, cb1, cw2, (float*)d_out);
}